// round 16
// baseline (speedup 1.0000x reference)
#include <cuda_runtime.h>
#include <float.h>
#include <math.h>

#define BATCH 2
#define NPTS 8192
#define KNN 16
#define THREADS 256                     // 4 co-op quarter-groups of 64
#define QPB 64                          // queries per block
#define NSPLIT 4
#define QTR_PTS (NPTS / NSPLIT)         // 2048 ref points per quarter-thread
#define TILE 256                        // staged points per quarter per iteration
#define SUB 512                         // threshold subset (ref[0:512])
#define NBLOCKS (2 * BATCH * NPTS / QPB)       // 512
#define NQ_TOTAL (2 * BATCH * NPTS)            // 32768
#define CAP 256                         // floats per (query, quarter) row: E~126, big margin
#define MP  (KNN + 1)                   // merge pitch 17
#define MP8 9                           // top-8 merge pitch
#define POOL_FLOATS (NSPLIT * QPB * MP) // 4352 floats = 17.4 KB

__device__ float g_partials[NBLOCKS];
__device__ unsigned int g_done;                              // zero-init; self-resets
__device__ float g_scratch[(size_t)NSPLIT * CAP * NQ_TOTAL]; // 134 MB static

// packed fp32x2 fma: d = a*b + c
#define FMA2(d, a, b, c) \
    asm("fma.rn.f32x2 %0, %1, %2, %3;" : "=l"(d) : "l"(a), "l"(b), "l"(c))
#define PACK2(d, lo, hi) \
    asm("mov.b64 %0, {%1, %2};" : "=l"(d) : "f"(lo), "f"(hi))
#define UNPACK2(lo, hi, s) \
    asm("mov.b64 {%0, %1}, %2;" : "=f"(lo), "=f"(hi) : "l"(s))

// pair-packed branch-free emit: if min(s0,s1) <= tau, store BOTH (v2) and
// advance 2 slots. Extra stored values are a harmless superset for selection.
__device__ __forceinline__ float* cond_store2(float* wp, float s0, float s1, float tau) {
    const float m = fminf(s0, s1);
    asm volatile(
        "{\n\t"
        ".reg .pred p;\n\t"
        ".reg .u64 inc;\n\t"
        "setp.le.f32 p, %1, %4;\n\t"
        "selp.u64 inc, 8, 0, p;\n\t"
        "@p st.global.v2.f32 [%0], {%2, %3};\n\t"
        "add.u64 %0, %0, inc;\n\t"
        "}"
        : "+l"(wp)
        : "f"(m), "f"(s0), "f"(s1), "f"(tau)
        : "memory");
    return wp;
}

// unconditional sorted-descending top-16 insert (31 FMNMX)
__device__ __forceinline__ void bubble16(float* b, float sc) {
    b[0] = fminf(b[0], sc);
#pragma unroll
    for (int i = 0; i < KNN - 1; i++) {
        const float a = b[i], c = b[i + 1];
        b[i] = fmaxf(a, c); b[i + 1] = fminf(a, c);
    }
}
// unconditional sorted-descending top-8 insert (15 FMNMX)
__device__ __forceinline__ void bubble8(float* b, float sc) {
    b[0] = fminf(b[0], sc);
#pragma unroll
    for (int i = 0; i < 7; i++) {
        const float a = b[i], c = b[i + 1];
        b[i] = fmaxf(a, c); b[i + 1] = fminf(a, c);
    }
}

// score 4 consecutive SoA points with packed f32x2 fma
__device__ __forceinline__ void score4(const float* sx, const float* sy,
                                       const float* sz, const float* sw, int j,
                                       unsigned long long nqx2, unsigned long long nqy2,
                                       unsigned long long nqz2, float* sc) {
    const ulonglong2 X = *(const ulonglong2*)(sx + j);   // LDS.128 -> 2 aligned pairs
    const ulonglong2 Y = *(const ulonglong2*)(sy + j);
    const ulonglong2 Z = *(const ulonglong2*)(sz + j);
    const ulonglong2 W = *(const ulonglong2*)(sw + j);
    unsigned long long s01, s23;
    FMA2(s01, nqx2, X.x, W.x); FMA2(s01, nqy2, Y.x, s01); FMA2(s01, nqz2, Z.x, s01);
    FMA2(s23, nqx2, X.y, W.y); FMA2(s23, nqy2, Y.y, s23); FMA2(s23, nqz2, Z.y, s23);
    UNPACK2(sc[0], sc[1], s01);
    UNPACK2(sc[2], sc[3], s23);
}

__global__ void __launch_bounds__(THREADS, 4)
chamfer_knn_kernel(const float* __restrict__ src,
                   const float* __restrict__ tgt,
                   const float* __restrict__ flow,
                   float* __restrict__ out) {
    // time-shared pool: tau SoA (2048) / top8 merge (2304) / tiles (4096) / top16 merge (4352)
    __shared__ __align__(16) float pool[POOL_FLOATS];
    __shared__ float warpsum[THREADS / 32];
    __shared__ unsigned int s_rank;

    const int tid = threadIdx.x;
    const int q   = tid >> 6;                 // quarter group 0..3
    const int lt  = tid & 63;                 // query lane
    const int gq  = blockIdx.x * QPB + lt;

    const int set = gq / NPTS;                // 0..3 : (batch, direction)
    const int b   = set >> 1;
    const int dir = set & 1;                  // 0: pred->target, 1: target->pred
    const int qi  = gq - set * NPTS;

    const float* __restrict__ srcb = src  + (size_t)b * NPTS * 3;
    const float* __restrict__ tgtb = tgt  + (size_t)b * NPTS * 3;
    const float* __restrict__ flob = flow + (size_t)b * NPTS * 3;

    float qx, qy, qz;
    if (dir == 0) {
        qx = srcb[qi * 3 + 0] + flob[qi * 3 + 0];
        qy = srcb[qi * 3 + 1] + flob[qi * 3 + 1];
        qz = srcb[qi * 3 + 2] + flob[qi * 3 + 2];
    } else {
        qx = tgtb[qi * 3 + 0];
        qy = tgtb[qi * 3 + 1];
        qz = tgtb[qi * 3 + 2];
    }
    const float q2 = qx * qx + qy * qy + qz * qz;

    unsigned long long nqx2, nqy2, nqz2;
    PACK2(nqx2, -qx, -qx); PACK2(nqy2, -qy, -qy); PACK2(nqz2, -qz, -qz);

    // ---------------- cooperative tau over ref[0:512] ----------------
    for (int p = tid; p < SUB; p += THREADS) {
        float x, y, z;
        if (dir == 0) {
            x = tgtb[p * 3 + 0]; y = tgtb[p * 3 + 1]; z = tgtb[p * 3 + 2];
        } else {
            x = srcb[p * 3 + 0] + flob[p * 3 + 0];
            y = srcb[p * 3 + 1] + flob[p * 3 + 1];
            z = srcb[p * 3 + 2] + flob[p * 3 + 2];
        }
        pool[p]        = x;
        pool[p + 512]  = y;
        pool[p + 1024] = z;
        pool[p + 1536] = 0.5f * (x * x + (y * y + z * z));
    }
    __syncthreads();

    float best8[8];
#pragma unroll
    for (int i = 0; i < 8; i++) best8[i] = FLT_MAX;

    // each quarter-thread keeps top-8 of its disjoint 128-point slice
    for (int j0 = q * 128; j0 < q * 128 + 128; j0 += 8) {
        float sc[8];
        score4(pool, pool + 512, pool + 1024, pool + 1536, j0,     nqx2, nqy2, nqz2, sc);
        score4(pool, pool + 512, pool + 1024, pool + 1536, j0 + 4, nqx2, nqy2, nqz2, sc + 4);
#pragma unroll
        for (int jj = 0; jj < 8; jj++) bubble8(best8, sc[jj]);
    }
    __syncthreads();          // subset reads done before pool reuse

    {   // publish top-8 (pitch 9)
        float* dst = pool + (q * QPB + lt) * MP8;
#pragma unroll
        for (int i = 0; i < 8; i++) dst[i] = best8[i];
    }
    __syncthreads();

    float best[KNN];
#pragma unroll
    for (int i = 0; i < KNN; i++) best[i] = FLT_MAX;
    // 16th-smallest of the 32 collected values: valid upper bound on true 16th
#pragma unroll
    for (int oq = 0; oq < NSPLIT; oq++) {
        const float* sl = pool + (oq * QPB + lt) * MP8;
#pragma unroll
        for (int i = 0; i < 8; i++) bubble16(best, sl[i]);
    }
    float tau = best[0];
    __syncthreads();          // merge reads done before tiles overwrite

    // ---------------- scan this thread's ref quarter (SoA tiles) ----------------
    float* const sxq = pool + q * (TILE * 4);
    float* const syq = sxq + TILE;
    float* const szq = sxq + 2 * TILE;
    float* const swq = sxq + 3 * TILE;

    // row-major candidate row: contiguous CAP floats per (query, quarter)
    float* const wbase  = g_scratch + ((size_t)q * NQ_TOTAL + gq) * CAP;
    float*       wp     = wbase;
    float* const wguard = wbase + (CAP - 64);   // belt slack: 64 pts/check -> <=64 floats

    for (int t0 = 0; t0 < QTR_PTS; t0 += TILE) {
#pragma unroll
        for (int k = 0; k < TILE / QPB; k++) {
            const int p = lt + k * QPB;
            const int g = q * QTR_PTS + t0 + p;
            float x, y, z;
            if (dir == 0) {
                x = tgtb[g * 3 + 0]; y = tgtb[g * 3 + 1]; z = tgtb[g * 3 + 2];
            } else {
                x = srcb[g * 3 + 0] + flob[g * 3 + 0];
                y = srcb[g * 3 + 1] + flob[g * 3 + 1];
                z = srcb[g * 3 + 2] + flob[g * 3 + 2];
            }
            sxq[p] = x; syq[p] = y; szq[p] = z;
            swq[p] = 0.5f * (x * x + (y * y + z * z));
        }
        __syncthreads();

        for (int j0 = 0; j0 < TILE; j0 += 64) {
            tau = (wp >= wguard) ? -FLT_MAX : tau;   // belt; never fires statistically
#pragma unroll
            for (int g4 = 0; g4 < 64; g4 += 4) {
                float sc[4];
                score4(sxq, syq, szq, swq, j0 + g4, nqx2, nqy2, nqz2, sc);
                wp = cond_store2(wp, sc[0], sc[1], tau);
                wp = cond_store2(wp, sc[2], sc[3], tau);
            }
        }
        __syncthreads();
    }

    // ---------------- per-quarter exact selection (row reads, float4) ----------------
    const int cnt  = (int)(wp - wbase);
    const int mcnt = __reduce_max_sync(0xffffffffu, cnt);
#pragma unroll
    for (int i = 0; i < KNN; i++) best[i] = FLT_MAX;

    for (int i = 0; i < mcnt; i += 4) {
        const float4 t4 = *(const float4*)(wbase + i);   // row is 16B aligned (CAP*4B)
        float v[4] = {t4.x, t4.y, t4.z, t4.w};
#pragma unroll
        for (int u = 0; u < 4; u++) {
            v[u] = (i + u < cnt) ? v[u] : FLT_MAX;
            bubble16(best, v[u]);
        }
    }

    // ---------------- merge quarters (pitch 17) ----------------
    if (q != 0) {
        float* dst = pool + (q * QPB + lt) * MP;
#pragma unroll
        for (int i = 0; i < KNN; i++) dst[i] = best[i];
    }
    __syncthreads();

    float s = 0.f;
    if (q == 0) {
#pragma unroll
        for (int oq = 1; oq < NSPLIT; oq++) {
            const float* sl = pool + (oq * QPB + lt) * MP;
#pragma unroll
            for (int i = 0; i < KNN; i++) bubble16(best, sl[i]);
        }
#pragma unroll
        for (int i = 0; i < KNN; i++) {
            const float d2 = fmaf(2.f, best[i], q2);
            s += sqrtf(fmaxf(d2, 0.f));
        }
    }

    // deterministic block + global reduction
#pragma unroll
    for (int o = 16; o > 0; o >>= 1) s += __shfl_down_sync(0xffffffffu, s, o);
    if ((tid & 31) == 0) warpsum[tid >> 5] = s;
    __syncthreads();

    if (tid == 0) {
        float tot = 0.f;
#pragma unroll
        for (int w = 0; w < THREADS / 32; w++) tot += warpsum[w];
        g_partials[blockIdx.x] = tot;
        __threadfence();
        s_rank = atomicAdd(&g_done, 1u);
    }
    __syncthreads();
    if (tid == 0 && s_rank == NBLOCKS - 1) {
        float tot = 0.f;                 // fixed-order -> bitwise deterministic
        for (int i = 0; i < NBLOCKS; i++) tot += g_partials[i];
        out[0] = tot * (1.0f / (float)(KNN * BATCH * NPTS));
        g_done = 0;                      // self-reset for next graph replay
    }
}

extern "C" void kernel_launch(void* const* d_in, const int* in_sizes, int n_in,
                              void* d_out, int out_size) {
    const float* src  = (const float*)d_in[0];   // pc_source [B, N, 3]
    const float* tgt  = (const float*)d_in[1];   // pc_target [B, M, 3]
    const float* flow = (const float*)d_in[2];   // pred_flow [B, N, 3]
    float* out = (float*)d_out;

    chamfer_knn_kernel<<<NBLOCKS, THREADS>>>(src, tgt, flow, out);
}